// round 13
// baseline (speedup 1.0000x reference)
#include <cuda_runtime.h>

// ---------------------------------------------------------------------------
// OctreeInterp R12 (= R10, third attempt; R11/R12 hit container failures):
//   - presence bitmaps packed 2 buckets/u32 -> 8 MB table, L2-resident
//     (probe = one u32 load; bucket-pair locality free)
//   - start indices in separate 16 MB u32 table, loaded ONLY on bitmap hit
//   - 2 threads per point (even lane ch 0-15, odd ch 16-31), merged probes
//   - idempotent build: atomicOr for bitmaps, single-writer store for starts
// ---------------------------------------------------------------------------

#define DEPTH      8
#define KEY_BITS   26
#define NB_LOG     22
#define NB         (1 << NB_LOG)
#define SHIFT      (KEY_BITS - NB_LOG)   // 4

__device__ unsigned g_bm[NB / 2];     // 8 MB, zero-init: bitmap pairs
__device__ unsigned g_start[NB];      // 16 MB: bucket start idx (hit-path only)

__global__ void build_kernel(const int* __restrict__ keys, int H) {
    int i = blockIdx.x * blockDim.x + threadIdx.x;
    if (i >= H) return;
    int k = keys[i];
    int t = k >> SHIFT;
    atomicOr(&g_bm[t >> 1], 1u << (((t & 1) << 4) + (k & 15)));
    // unique boundary writer per non-empty bucket; idempotent plain store
    if (i == 0 || (__ldg(&keys[i - 1]) >> SHIFT) != t)
        g_start[t] = (unsigned)i;
}

__device__ __forceinline__ int spread3(int v) {
    v &= 0xFF;
    v = (v | (v << 8)) & 0x00F00F;
    v = (v | (v << 4)) & 0x0C30C3;
    v = (v | (v << 2)) & 0x249249;
    return v;
}

__global__ void __launch_bounds__(256, 6)
interp_kernel(const float*  __restrict__ data,      // [H,32]
              const float4* __restrict__ pts,       // [N]
              const int*    __restrict__ keys,      // [H] sorted
              float4*       __restrict__ outv,      // [N*8] float4 view
              int N2) {                             // N2 = 2*N
    int t = blockIdx.x * 256 + threadIdx.x;
    if (t >= N2) return;

    int n    = t >> 1;                 // point index
    int half = t & 1;                  // 0: ch 0-15, 1: ch 16-31

    float4 p = __ldcs(&pts[n]);        // pair lanes: same line, merged

    // xf = (x + 1) * 128 - 0.5, unfused to match reference f32 ops
    float xf = __fadd_rn(__fmul_rn(__fadd_rn(p.x, 1.0f), 128.0f), -0.5f);
    float yf = __fadd_rn(__fmul_rn(__fadd_rn(p.y, 1.0f), 128.0f), -0.5f);
    float zf = __fadd_rn(__fmul_rn(__fadd_rn(p.z, 1.0f), 128.0f), -0.5f);

    float xfl = floorf(xf), yfl = floorf(yf), zfl = floorf(zf);
    float fx = __fsub_rn(xf, xfl);
    float fy = __fsub_rn(yf, yfl);
    float fz = __fsub_rn(zf, zfl);
    int xi = (int)xfl, yi = (int)yfl, zi = (int)zfl;

    int bb = ((int)p.w) << (3 * DEPTH);

    int sx0 = spread3(xi)     << 2, sx1 = spread3(xi + 1) << 2;
    int sy0 = spread3(yi)     << 1, sy1 = spread3(yi + 1) << 1;
    int sz0 = spread3(zi),          sz1 = spread3(zi + 1);

    int key[8];
    #pragma unroll
    for (int c = 0; c < 8; ++c)
        key[c] = bb | ((c & 4) ? sx1 : sx0)
                    | ((c & 2) ? sy1 : sy0)
                    | ((c & 1) ? sz1 : sz0);

    // 8 independent bitmap probes into the 8 MB L2-resident table
    unsigned bmv[8];
    #pragma unroll
    for (int c = 0; c < 8; ++c)
        bmv[c] = __ldg(&g_bm[key[c] >> (SHIFT + 1)]);

    unsigned vm = 0;
    #pragma unroll
    for (int c = 0; c < 8; ++c) {
        int tb = key[c] >> SHIFT;
        unsigned bit = ((tb & 1) << 4) + (key[c] & 15);
        if ((bmv[c] >> bit) & 1u) vm |= (1u << c);
    }

    float4* o = &outv[(size_t)n * 8 + half * 4];

    if (vm == 0) {                     // ~76% of points: exact zeros
        float4 z = make_float4(0.f, 0.f, 0.f, 0.f);
        #pragma unroll
        for (int j = 0; j < 4; ++j) __stcs(&o[j], z);
        return;
    }

    float wx0 = 1.0f - fx, wy0 = 1.0f - fy, wz0 = 1.0f - fz;

    float4 acc[4];
    #pragma unroll
    for (int j = 0; j < 4; ++j) acc[j] = make_float4(0.f, 0.f, 0.f, 0.f);
    float wsum = 0.0f;

    #pragma unroll
    for (int c = 0; c < 8; ++c) {
        if (vm & (1u << c)) {
            // hit path (~3% of corners): start index + short forward scan
            int pp = (int)__ldg(&g_start[key[c] >> SHIFT]);
            while (__ldg(&keys[pp]) < key[c]) ++pp;   // first occurrence

            float wc = ((c & 4) ? fx : wx0) *
                       ((c & 2) ? fy : wy0) *
                       ((c & 1) ? fz : wz0);
            wsum += wc;
            const float4* row = (const float4*)(data + (size_t)pp * 32) + half * 4;
            #pragma unroll
            for (int j = 0; j < 4; ++j) {
                float4 f = __ldcs(&row[j]);
                acc[j].x += wc * f.x;
                acc[j].y += wc * f.y;
                acc[j].z += wc * f.z;
                acc[j].w += wc * f.w;
            }
        }
    }

    float inv = 1.0f / (wsum + 1e-12f);
    #pragma unroll
    for (int j = 0; j < 4; ++j) {
        float4 a = acc[j];
        a.x *= inv; a.y *= inv; a.z *= inv; a.w *= inv;
        __stcs(&o[j], a);
    }
}

extern "C" void kernel_launch(void* const* d_in, const int* in_sizes, int n_in,
                              void* d_out, int out_size) {
    const float*  data = (const float*)d_in[0];
    const float4* pts  = (const float4*)d_in[1];
    const int*    keys = (const int*)d_in[2];

    int N = in_sizes[1] / 4;
    int H = in_sizes[2];
    int N2 = 2 * N;

    build_kernel<<<(H + 255) / 256, 256>>>(keys, H);
    interp_kernel<<<(N2 + 255) / 256, 256>>>(data, pts, keys,
                                             (float4*)d_out, N2);
}